// round 7
// baseline (speedup 1.0000x reference)
#include <cuda_runtime.h>

#define NT 1096
#define NS 2048
#define NH 16
#define NL (NS*NH)        // 32768 lanes
#define NC 4              // time chunks
#define CL 274            // chunk length: 4*274 = 1096
#define NPB (NL/256)      // 128 lane-group blocks per chunk

// Scratch: published per-lane chunk summaries + per-block flags (~2 MB)
__device__ float g_A[NC*NL], g_B[NC*NL], g_C[NC*NL], g_hsum[NC*NL];
__device__ int   g_flagA[NC*NPB], g_flagB[NC*NPB];

__global__ void zero_flags() {
    int i = blockIdx.x * blockDim.x + threadIdx.x;
    if (i < NC*NPB) { g_flagA[i] = 0; g_flagB[i] = 0; }
}

__device__ __forceinline__ void snow_step(float Tk, float Pk, float melt,
                                          float& s, float& x) {
    const float sm   = fmaxf(Tk, 0.0f) * melt;
    const float m    = fminf(sm, s);
    const float pin  = (Tk < 0.0f) ? Pk : 0.0f;
    const float rain = (Tk > 0.0f) ? Pk : 0.0f;
    s = (s - m) + pin;
    x = rain + m;
}

__global__ __launch_bounds__(256, 4)
void fused_scan(const float* __restrict__ P, const float* __restrict__ T,
                const float* __restrict__ w_i, const float* __restrict__ w_o,
                const float* __restrict__ w_l, const float* __restrict__ w_s,
                float* __restrict__ Q, float* __restrict__ H, float* __restrict__ S)
{
    const int bid  = blockIdx.x;
    const int c    = bid >> 7;            // chunk (NPB = 128)
    const int b    = bid & (NPB - 1);     // lane group
    const int tid  = threadIdx.x;
    const int lane = b * 256 + tid;       // site*NH + h
    const int site = lane >> 4;
    const int h    = lane & 15;

    // Time-invariant gates
    const float melt = expf(w_s[h]) + 1.0f;
    const float gi   = 1.0f / (1.0f + expf(-w_i[h]));
    const float gl   = 1.0f / (1.0f + expf(-w_l[h]));
    float wmax = w_o[0];
    #pragma unroll
    for (int i = 1; i < NH; ++i) wmax = fmaxf(wmax, w_o[i]);
    float denom = 0.0f;
    #pragma unroll
    for (int i = 0; i < NH; ++i) denom += expf(w_o[i] - wmax);
    const float a = expf(w_o[h] - wmax) / denom;

    const float alpha = 1.0f - gl;
    const float gax   = alpha * gi;         // hs' = alpha*hs + gax*x
    const float ch    = a * gl / alpha;     // q*a = hs' * ch
    const float aL    = powf(alpha, (float)CL);

    const float* Pp = P + site;
    const float* Tp = T + site;
    float* Hp = H + lane;
    float* Sp = S + lane;
    float* Qp = Q + site;
    const int t0 = c * CL;

    float s0v = 0.0f, hs0 = 0.0f;

    if (c > 0) {
        // ── Phase A: fold snow step-operators f(s)=max(s-A,B)+C over this chunk ──
        float A = 0.0f, B = -1e30f, C = 0.0f;
        {
            float pb0 = Pp[(size_t)t0 * NS],       tb0 = Tp[(size_t)t0 * NS];
            float pb1 = Pp[(size_t)(t0 + 1) * NS], tb1 = Tp[(size_t)(t0 + 1) * NS];
            for (int t = t0; t < t0 + CL; t += 2) {
                const float pc0 = pb0, tc0 = tb0, pc1 = pb1, tc1 = tb1;
                if (t + 3 < t0 + CL) {
                    pb0 = Pp[(size_t)(t + 2) * NS]; tb0 = Tp[(size_t)(t + 2) * NS];
                    pb1 = Pp[(size_t)(t + 3) * NS]; tb1 = Tp[(size_t)(t + 3) * NS];
                }
                #pragma unroll
                for (int u = 0; u < 2; ++u) {
                    const float Tk = u ? tc1 : tc0;
                    const float Pk = u ? pc1 : pc0;
                    const float sm  = fmaxf(Tk, 0.0f) * melt;
                    const float pin = (Tk < 0.0f) ? Pk : 0.0f;
                    const float An = A + sm - C;
                    const float Bn = fmaxf(B + C - sm, 0.0f);
                    A = An; B = Bn; C = pin;
                }
            }
        }
        const int idx = c * NL + lane;
        g_A[idx] = A; g_B[idx] = B; g_C[idx] = C;
        __syncthreads();
        if (tid == 0) { __threadfence(); atomicExch(&g_flagA[c * NPB + b], 1); }

        // ── Look-back: compose predecessors' operators -> exact incoming s0 ──
        if (tid == 0) {
            for (int cp = 0; cp < c; ++cp)
                while (atomicAdd(&g_flagA[cp * NPB + b], 0) == 0) __nanosleep(64);
            __threadfence();
        }
        __syncthreads();
        float s = 0.0f;
        for (int cp = 0; cp < c; ++cp) {
            const int i = cp * NL + lane;
            s = fmaxf(s - g_A[i], g_B[i]) + g_C[i];
        }
        s0v = s;

        // ── Phase B: replay snow from s0, fold linear bucket (hs0 = 0) ──
        float hs = 0.0f;
        {
            float pb0 = Pp[(size_t)t0 * NS],       tb0 = Tp[(size_t)t0 * NS];
            float pb1 = Pp[(size_t)(t0 + 1) * NS], tb1 = Tp[(size_t)(t0 + 1) * NS];
            for (int t = t0; t < t0 + CL; t += 2) {
                const float pc0 = pb0, tc0 = tb0, pc1 = pb1, tc1 = tb1;
                if (t + 3 < t0 + CL) {
                    pb0 = Pp[(size_t)(t + 2) * NS]; tb0 = Tp[(size_t)(t + 2) * NS];
                    pb1 = Pp[(size_t)(t + 3) * NS]; tb1 = Tp[(size_t)(t + 3) * NS];
                }
                float x;
                snow_step(tc0, pc0, melt, s, x);
                hs = alpha * hs + gax * x;
                snow_step(tc1, pc1, melt, s, x);
                hs = alpha * hs + gax * x;
            }
        }
        g_hsum[idx] = hs;
        __syncthreads();
        if (tid == 0) { __threadfence(); atomicExch(&g_flagB[c * NPB + b], 1); }

        // ── Look-back: affine fold -> exact incoming hs0 ──
        if (tid == 0) {
            for (int cp = 0; cp < c; ++cp)
                while (atomicAdd(&g_flagB[cp * NPB + b], 0) == 0) __nanosleep(64);
            __threadfence();
        }
        __syncthreads();
        float hh = 0.0f;
        for (int cp = 0; cp < c; ++cp)
            hh = aL * hh + g_hsum[cp * NL + lane];
        hs0 = hh;
    }

    // ── Output pass: replay from exact (s0, hs0); write Q, H, S ──
    // (For chunk 0 this doubles as phases A+B: its end state publishes
    //  a constant operator and its hs equals hsum.)
    float s  = s0v;
    float hs = hs0;
    {
        float pb0 = Pp[(size_t)t0 * NS],       tb0 = Tp[(size_t)t0 * NS];
        float pb1 = Pp[(size_t)(t0 + 1) * NS], tb1 = Tp[(size_t)(t0 + 1) * NS];
        for (int t = t0; t < t0 + CL; t += 2) {
            const float pc0 = pb0, tc0 = tb0, pc1 = pb1, tc1 = tb1;
            if (t + 3 < t0 + CL) {
                pb0 = Pp[(size_t)(t + 2) * NS]; tb0 = Tp[(size_t)(t + 2) * NS];
                pb1 = Pp[(size_t)(t + 3) * NS]; tb1 = Tp[(size_t)(t + 3) * NS];
            }
            #pragma unroll
            for (int u = 0; u < 2; ++u) {
                const float Tk = u ? tc1 : tc0;
                const float Pk = u ? pc1 : pc0;
                float x;
                snow_step(Tk, Pk, melt, s, x);
                hs = alpha * hs + gax * x;

                const size_t off = (size_t)(t + u) * (size_t)NL;
                Hp[off] = hs;
                Sp[off] = s;

                float qa = hs * ch;
                qa += __shfl_xor_sync(0xffffffffu, qa, 1);
                qa += __shfl_xor_sync(0xffffffffu, qa, 2);
                qa += __shfl_xor_sync(0xffffffffu, qa, 4);
                qa += __shfl_xor_sync(0xffffffffu, qa, 8);
                if (h == 0) Qp[(size_t)(t + u) * NS] = qa;
            }
        }
    }

    if (c == 0) {
        // Publish chunk 0's inclusive results: constant snow operator
        // f(s)=max(s-1e30, 0)+s_end == s_end, and hsum = hs (since hs0=0).
        g_A[lane] = 1e30f; g_B[lane] = 0.0f; g_C[lane] = s; g_hsum[lane] = hs;
        __syncthreads();
        if (tid == 0) {
            __threadfence();
            atomicExch(&g_flagA[b], 1);
            atomicExch(&g_flagB[b], 1);
        }
    }
}

extern "C" void kernel_launch(void* const* d_in, const int* in_sizes, int n_in,
                              void* d_out, int out_size) {
    const float* P   = (const float*)d_in[0];
    const float* T   = (const float*)d_in[1];
    const float* w_i = (const float*)d_in[2];
    const float* w_o = (const float*)d_in[3];
    const float* w_l = (const float*)d_in[4];
    const float* w_s = (const float*)d_in[5];

    float* out = (float*)d_out;
    float* Q = out;                                           // [NT, NS]
    float* H = out + (size_t)NT * NS;                         // [NT, NS, NH]
    float* S = out + (size_t)NT * NS + (size_t)NT * NS * NH;  // [NT, NS, NH]

    zero_flags<<<(NC*NPB + 255) / 256, 256>>>();
    fused_scan<<<NC * NPB, 256>>>(P, T, w_i, w_o, w_l, w_s, Q, H, S);
}

// round 8
// speedup vs baseline: 1.7190x; 1.7190x over previous
#include <cuda_runtime.h>

#define NT 1096
#define NS 2048
#define NH 16
#define NL (NS*NH)          // 32768 output lanes
#define NP (NL/2)           // 16384 pair-threads
#define UF 8                // NT = 8 * 137

__global__ __launch_bounds__(128)
void waternet_kernel(const float* __restrict__ P, const float* __restrict__ T,
                     const float* __restrict__ w_i, const float* __restrict__ w_o,
                     const float* __restrict__ w_l, const float* __restrict__ w_s,
                     float* __restrict__ Q, float* __restrict__ H, float* __restrict__ S)
{
    const int pid  = blockIdx.x * blockDim.x + threadIdx.x;   // [0, NP)
    const int site = pid >> 3;          // 8 h-pairs per site
    const int hp   = pid & 7;           // h-pair index within site
    const int h0   = hp * 2;
    const int h1   = h0 + 1;

    // Gates for both h lanes
    const float melt0 = expf(w_s[h0]) + 1.0f;
    const float melt1 = expf(w_s[h1]) + 1.0f;
    const float gi0   = 1.0f / (1.0f + expf(-w_i[h0]));
    const float gi1   = 1.0f / (1.0f + expf(-w_i[h1]));
    const float gl0   = 1.0f / (1.0f + expf(-w_l[h0]));
    const float gl1   = 1.0f / (1.0f + expf(-w_l[h1]));

    float wmax = w_o[0];
    #pragma unroll
    for (int i = 1; i < NH; ++i) wmax = fmaxf(wmax, w_o[i]);
    float denom = 0.0f;
    #pragma unroll
    for (int i = 0; i < NH; ++i) denom += expf(w_o[i] - wmax);
    const float a0 = expf(w_o[h0] - wmax) / denom;
    const float a1 = expf(w_o[h1] - wmax) / denom;

    // LinearBucket identity: hs' = alpha*hs + (alpha*gi)*x ; q*a = hs' * ch
    const float alpha0 = 1.0f - gl0, alpha1 = 1.0f - gl1;
    const float gax0 = alpha0 * gi0,  gax1 = alpha1 * gi1;
    const float ch0  = a0 * gl0 / alpha0;
    const float ch1  = a1 * gl1 / alpha1;

    float s0 = 0.0f, s1 = 0.0f, hs0 = 0.0f, hs1 = 0.0f;

    const float* Pp = P + site;
    const float* Tp = T + site;
    float2* Hp = (float2*)(H) + ((site << 4) + h0) / 2;   // [t][site][h] as float2
    float2* Sp = (float2*)(S) + ((site << 4) + h0) / 2;
    float*  Qp = Q + site;

    const bool bt4 = (hp & 4) != 0;
    const bool bt2 = (hp & 2) != 0;
    const bool bt1 = (hp & 1) != 0;

    // Initial prefetch of group 0
    float pb[UF], tb[UF];
    #pragma unroll
    for (int i = 0; i < UF; ++i) {
        pb[i] = Pp[i * NS];
        tb[i] = Tp[i * NS];
    }

    for (int t0 = 0; t0 < NT; t0 += UF) {
        const bool more = (t0 + UF) < NT;
        float qa[UF];

        #pragma unroll
        for (int i = 0; i < UF; ++i) {
            const float Pk = pb[i];
            const float Tk = tb[i];
            // Spread prefetch: reload slot i for next group (distance = 8 iters)
            if (more) {
                pb[i] = Pp[(t0 + UF + i) * NS];
                tb[i] = Tp[(t0 + UF + i) * NS];
            }

            const float warm = fmaxf(Tk, 0.0f);
            const float pin  = (Tk < 0.0f) ? Pk : 0.0f;
            const float rain = (Tk > 0.0f) ? Pk : 0.0f;

            // chain h0
            const float m0 = fminf(warm * melt0, s0);
            s0 = (s0 - m0) + pin;
            hs0 = alpha0 * hs0 + gax0 * (rain + m0);
            // chain h1 (independent of chain h0 -> ILP)
            const float m1 = fminf(warm * melt1, s1);
            s1 = (s1 - m1) + pin;
            hs1 = alpha1 * hs1 + gax1 * (rain + m1);

            const int off2 = (t0 + i) * NP;       // float2 stride per t
            Hp[off2] = make_float2(hs0, hs1);
            Sp[off2] = make_float2(s0, s1);

            qa[i] = hs0 * ch0 + hs1 * ch1;        // this pair's q*a contribution
        }

        // Value-split reduction: 8 values over the 8-lane group in 7 SHFLs.
        // After the tree, group-lane g holds the full sum for timestep t0+g.
        #pragma unroll
        for (int i = 0; i < 4; ++i) {
            const float send = bt4 ? qa[i] : qa[i + 4];
            const float recv = __shfl_xor_sync(0xffffffffu, send, 4);
            const float keep = bt4 ? qa[i + 4] : qa[i];
            qa[i] = keep + recv;
        }
        #pragma unroll
        for (int i = 0; i < 2; ++i) {
            const float send = bt2 ? qa[i] : qa[i + 2];
            const float recv = __shfl_xor_sync(0xffffffffu, send, 2);
            const float keep = bt2 ? qa[i + 2] : qa[i];
            qa[i] = keep + recv;
        }
        {
            const float send = bt1 ? qa[0] : qa[1];
            const float recv = __shfl_xor_sync(0xffffffffu, send, 1);
            const float keep = bt1 ? qa[1] : qa[0];
            qa[0] = keep + recv;
        }

        Qp[(t0 + hp) * NS] = qa[0];   // every lane stores its own t-row
    }
}

extern "C" void kernel_launch(void* const* d_in, const int* in_sizes, int n_in,
                              void* d_out, int out_size) {
    const float* P   = (const float*)d_in[0];
    const float* T   = (const float*)d_in[1];
    const float* w_i = (const float*)d_in[2];
    const float* w_o = (const float*)d_in[3];
    const float* w_l = (const float*)d_in[4];
    const float* w_s = (const float*)d_in[5];

    float* out = (float*)d_out;
    float* Q = out;                                           // [NT, NS]
    float* H = out + (size_t)NT * NS;                         // [NT, NS, NH]
    float* S = out + (size_t)NT * NS + (size_t)NT * NS * NH;  // [NT, NS, NH]

    const int block = 128;
    const int grid  = NP / block;       // 128 blocks, 1 per SM (uniform)
    waternet_kernel<<<grid, block>>>(P, T, w_i, w_o, w_l, w_s, Q, H, S);
}